// round 13
// baseline (speedup 1.0000x reference)
#include <cuda_runtime.h>
#include <cuda_bf16.h>
#include <math.h>
#include <stdint.h>

// Problem dims
#define B_   16
#define T_   512
#define C_   2048
#define H_   16
#define HD_  128
#define N3_  6144   // 3*C
#define M_   8192   // B*T
#define K3_  6144   // split-K (hi|lo|hi concatenation) for both GEMMs
#define KC_  64
#define NT_  (K3_ / KC_)

// ---------------- scratch (device globals; no runtime allocation) ----------
__device__ float          g_qkv  [(size_t)M_ * N3_];            // [B*T, 3*C] fp32
__device__ __nv_bfloat16  g_q2   [(size_t)B_ * H_ * T_ * 256];  // [B,H,T, hi128|lo128]
__device__ __nv_bfloat16  g_k2   [(size_t)B_ * H_ * T_ * 256];
__device__ __nv_bfloat16  g_v2   [(size_t)B_ * H_ * T_ * 256];
__device__ __nv_bfloat16  g_a2   [(size_t)M_ * K3_];            // [M, 3K] = [x_hi | x_lo | x_hi]
__device__ __nv_bfloat16  g_b2q  [(size_t)N3_ * K3_];           // [6144, 3K] = [W_hi | W_hi | W_lo]
__device__ __nv_bfloat16  g_b2o  [(size_t)C_ * K3_];            // [2048, 3K]
__device__ __nv_bfloat16  g_y2   [(size_t)M_ * K3_];            // attention out, split layout

// ===================== helpers ==============================================
__device__ __forceinline__ uint32_t smem_u32(const void* p) {
    uint32_t a;
    asm("{ .reg .u64 t; cvta.to.shared.u64 t, %1; cvt.u32.u64 %0, t; }" : "=r"(a) : "l"(p));
    return a;
}
__device__ __forceinline__ void cp16(uint32_t dst, const void* src) {
    asm volatile("cp.async.cg.shared.global [%0], [%1], 16;" :: "r"(dst), "l"(src));
}
#define CP_COMMIT()  asm volatile("cp.async.commit_group;" ::: "memory")
#define CP_WAIT1()   asm volatile("cp.async.wait_group 1;" ::: "memory")
#define SW128(off) ((off) ^ (((off) >> 3) & 0x70))

#define LDX4(a, addr) asm volatile( \
    "ldmatrix.sync.aligned.m8n8.x4.shared.b16 {%0,%1,%2,%3}, [%4];" \
    : "=r"((a)[0]), "=r"((a)[1]), "=r"((a)[2]), "=r"((a)[3]) : "r"(addr))
#define LDX2(bq, addr) asm volatile( \
    "ldmatrix.sync.aligned.m8n8.x2.shared.b16 {%0,%1}, [%2];" \
    : "=r"((bq)[0]), "=r"((bq)[1]) : "r"(addr))
#define LDX2T(bq, addr) asm volatile( \
    "ldmatrix.sync.aligned.m8n8.x2.trans.shared.b16 {%0,%1}, [%2];" \
    : "=r"((bq)[0]), "=r"((bq)[1]) : "r"(addr))
#define MMA16816(c, a, bq) asm volatile( \
    "mma.sync.aligned.m16n8k16.row.col.f32.bf16.bf16.f32 " \
    "{%0,%1,%2,%3}, {%4,%5,%6,%7}, {%8,%9}, {%0,%1,%2,%3};" \
    : "+f"((c)[0]), "+f"((c)[1]), "+f"((c)[2]), "+f"((c)[3]) \
    : "r"((a)[0]), "r"((a)[1]), "r"((a)[2]), "r"((a)[3]), "r"((bq)[0]), "r"((bq)[1]))

__device__ __forceinline__ uint32_t pack2(float a, float b) {
    __nv_bfloat162 t = __floats2bfloat162_rn(a, b);
    return *reinterpret_cast<uint32_t*>(&t);
}
__device__ __forceinline__ float bf16_round(float a) {
    return __bfloat162float(__float2bfloat16(a));
}

// ===================== conversion kernels ===================================
__global__ void conv_a_kernel(const float* __restrict__ X, __nv_bfloat16* __restrict__ A2)
{
    const int idx = blockIdx.x * 256 + threadIdx.x;
    const int e = idx << 2;
    const int m = e >> 11;
    const int k = e & 2047;
    const float4 v = *(const float4*)&X[(size_t)e];
    const float h0 = bf16_round(v.x), h1 = bf16_round(v.y);
    const float h2 = bf16_round(v.z), h3 = bf16_round(v.w);
    uint2 hp, lp;
    hp.x = pack2(h0, h1); hp.y = pack2(h2, h3);
    lp.x = pack2(v.x - h0, v.y - h1); lp.y = pack2(v.z - h2, v.w - h3);
    const size_t ro = (size_t)m * K3_;
    *(uint2*)&A2[ro + k]        = hp;
    *(uint2*)&A2[ro + 2048 + k] = lp;
    *(uint2*)&A2[ro + 4096 + k] = hp;
}

__global__ void conv_w_kernel(const float* __restrict__ W, __nv_bfloat16* __restrict__ B2, int N)
{
    __shared__ float tile[32][33];
    const int n0 = blockIdx.x << 5;
    const int k0 = blockIdx.y << 5;
    const int tid = threadIdx.x;
    const int c = tid & 31, rb = tid >> 5;
#pragma unroll
    for (int j = 0; j < 4; j++) {
        const int r = rb + (j << 3);
        tile[r][c] = W[(size_t)(k0 + r) * N + n0 + c];
    }
    __syncthreads();
#pragma unroll
    for (int j = 0; j < 4; j++) {
        const int nl = rb + (j << 3);
        const int kl = c;
        const float v = tile[kl][nl];
        const float h = bf16_round(v);
        const __nv_bfloat16 hb = __float2bfloat16(h);
        const __nv_bfloat16 lb = __float2bfloat16(v - h);
        const size_t ro = (size_t)(n0 + nl) * K3_ + k0 + kl;
        B2[ro]        = hb;
        B2[ro + 2048] = hb;
        B2[ro + 4096] = lb;
    }
}

// ===================== bf16 mma.sync GEMM ===================================
// 256x128 CTA tile, 512 threads (16 warps, 4x4), warp tile 64x32,
// K-chunk 64, 3-stage cp.async pipeline.
// Stage: A 256x128B (32KB) + B 128x128B (16KB) = 48KB; 3 stages = 144KB.
#define STG_BYTES 49152
#define G_SMEM_BYTES (3 * STG_BYTES)

__global__ __launch_bounds__(512, 1)
void gemm_mma(const __nv_bfloat16* __restrict__ A,
              const __nv_bfloat16* __restrict__ Bt,
              float* __restrict__ C, int N)
{
    extern __shared__ char sm[];
    const uint32_t sbase = smem_u32(sm);
    const int tid  = threadIdx.x;
    const int lane = tid & 31;
    const int w    = tid >> 5;      // 0..15
    const int wm   = w >> 2;        // 0..3  (M sub-tile)
    const int wn   = w & 3;         // 0..3  (N sub-tile)
    const int m0 = blockIdx.y << 8;
    const int n0 = blockIdx.x << 7;

    // ---- loader: thread covers 4 A rows (r0+64i) and 2 B rows (r0, r0+64)
    const int r0  = tid >> 3;       // 0..63
    const int c16 = tid & 7;
    // rows 64 apart share the same SW128 XOR term ((row&7)<<4)
    const uint32_t dswA = SW128((uint32_t)(r0 * 128 + c16 * 16));           // + i*8192
    const uint32_t dswB = 32768u + dswA;                                     // B region
    const char* Ag = (const char*)(A  + (size_t)(m0 + r0) * K3_) + c16 * 16;
    const char* Bg = (const char*)(Bt + (size_t)(n0 + r0) * K3_) + c16 * 16;
    const size_t rstep = (size_t)64 * K3_ * 2;   // 64 rows in bytes

    const int l15 = lane & 15;
    const int acg = (lane >> 4) & 1;
    const int l7  = lane & 7;
    const int bcg = (lane >> 3) & 1;
    const uint32_t xrA = (uint32_t)((l15 & 7) << 4);
    const uint32_t xrB = (uint32_t)(l7 << 4);
    uint32_t baseA[4], baseB[4];
#pragma unroll
    for (int mt = 0; mt < 4; mt++)
        baseA[mt] = (uint32_t)((wm * 64 + mt * 16 + l15) * 128);
#pragma unroll
    for (int nt = 0; nt < 4; nt++)
        baseB[nt] = (uint32_t)(32768 + (wn * 32 + nt * 8 + l7) * 128);

    float acc[4][4][4];
#pragma unroll
    for (int mt = 0; mt < 4; mt++)
#pragma unroll
        for (int nt = 0; nt < 4; nt++)
#pragma unroll
            for (int i = 0; i < 4; i++) acc[mt][nt][i] = 0.0f;

    // ---- prologue: stage chunks 0 and 1
#pragma unroll
    for (int pt = 0; pt < 2; pt++) {
        const uint32_t so = (uint32_t)pt * STG_BYTES;
        const char* ga = Ag + (size_t)pt * 128;
        const char* gb = Bg + (size_t)pt * 128;
#pragma unroll
        for (int i = 0; i < 4; i++)
            cp16(sbase + so + dswA + i * 8192, ga + (size_t)i * rstep);
#pragma unroll
        for (int i = 0; i < 2; i++)
            cp16(sbase + so + dswB + i * 8192, gb + (size_t)i * rstep);
        CP_COMMIT();
    }

    int buf = 0, nbuf = 2;
    for (int t = 0; t < NT_; t++) {
        CP_WAIT1();          // oldest pending group (chunk t) complete
        __syncthreads();
        {
            if (t + 2 < NT_) {
                const uint32_t so = (uint32_t)nbuf * STG_BYTES;
                const char* ga = Ag + (size_t)(t + 2) * 128;
                const char* gb = Bg + (size_t)(t + 2) * 128;
#pragma unroll
                for (int i = 0; i < 4; i++)
                    cp16(sbase + so + dswA + i * 8192, ga + (size_t)i * rstep);
#pragma unroll
                for (int i = 0; i < 2; i++)
                    cp16(sbase + so + dswB + i * 8192, gb + (size_t)i * rstep);
            }
            CP_COMMIT();
        }
        const uint32_t bufo = sbase + (uint32_t)buf * STG_BYTES;
#pragma unroll
        for (int ks = 0; ks < 4; ks++) {
            const uint32_t axo = ((uint32_t)(ks * 32 + acg * 16)) ^ xrA;
            const uint32_t bxo = ((uint32_t)(ks * 32 + bcg * 16)) ^ xrB;
            uint32_t a[4][4], b[4][2];
#pragma unroll
            for (int mt = 0; mt < 4; mt++)
                LDX4(a[mt], bufo + baseA[mt] + axo);
#pragma unroll
            for (int nt = 0; nt < 4; nt++)
                LDX2(b[nt], bufo + baseB[nt] + bxo);
#pragma unroll
            for (int mt = 0; mt < 4; mt++)
#pragma unroll
                for (int nt = 0; nt < 4; nt++)
                    MMA16816(acc[mt][nt], a[mt], b[nt]);
        }
        buf  = (buf  == 2) ? 0 : buf + 1;
        nbuf = (nbuf == 2) ? 0 : nbuf + 1;
    }

    const int gid = lane >> 2, tig = lane & 3;
#pragma unroll
    for (int mt = 0; mt < 4; mt++) {
        const int r = m0 + wm * 64 + mt * 16 + gid;
#pragma unroll
        for (int nt = 0; nt < 4; nt++) {
            const int cc = n0 + wn * 32 + nt * 8 + 2 * tig;
            float2 v0 = make_float2(acc[mt][nt][0], acc[mt][nt][1]);
            float2 v1 = make_float2(acc[mt][nt][2], acc[mt][nt][3]);
            *(float2*)&C[(size_t)r * N + cc]       = v0;
            *(float2*)&C[(size_t)(r + 8) * N + cc] = v1;
        }
    }
}

// ===================== RoPE + bf16 hi/lo split ==============================
__global__ void rope_split_kernel(const float* __restrict__ qkv,
                                  __nv_bfloat16* __restrict__ q2,
                                  __nv_bfloat16* __restrict__ k2,
                                  __nv_bfloat16* __restrict__ v2)
{
    __shared__ float s[64][132];
    const int bid = blockIdx.x;
    const int tt = bid & 7;
    const int h  = (bid >> 3) & 15;
    const int b  = bid >> 7;
    const int t0 = tt << 6;
    const int tid = threadIdx.x;
    const int bh = b * H_ + h;

    for (int which = 0; which < 3; which++) {
        __nv_bfloat16* dst = (which == 0) ? q2 : (which == 1) ? k2 : v2;
#pragma unroll
        for (int p = 0; p < 8; p++) {
            const int idx = tid + (p << 8);
            const int r  = idx >> 5;
            const int c4 = (idx & 31) << 2;
            const float4 v = *(const float4*)
                &qkv[((size_t)((b * T_ + t0 + r) * 3 + which)) * C_ + h * HD_ + c4];
            s[r][c4+0] = v.x; s[r][c4+1] = v.y; s[r][c4+2] = v.z; s[r][c4+3] = v.w;
        }
        __syncthreads();
        if (which < 2) {
            for (int it = tid; it < 512; it += 256) {
                const int r = it >> 3, d = it & 7;
                const float x1 = s[r][d], x2 = s[r][d + 8];
                const float inv = powf(10000.0f, -(float)d * 0.125f);
                const float ang = (float)(t0 + r) * inv;
                float sn, cs;
                sincosf(ang, &sn, &cs);
                s[r][d]     = x1 * cs - x2 * sn;
                s[r][d + 8] = x2 * cs + x1 * sn;
            }
        }
        __syncthreads();
#pragma unroll
        for (int p = 0; p < 8; p++) {
            const int idx = tid + (p << 8);
            const int r  = idx >> 5;
            const int c4 = (idx & 31) << 2;
            const float v0 = s[r][c4], v1 = s[r][c4+1], v2f = s[r][c4+2], v3 = s[r][c4+3];
            const float h0 = bf16_round(v0), h1 = bf16_round(v1);
            const float h2 = bf16_round(v2f), h3 = bf16_round(v3);
            uint2 hp, lp;
            hp.x = pack2(h0, h1); hp.y = pack2(h2, h3);
            lp.x = pack2(v0 - h0, v1 - h1); lp.y = pack2(v2f - h2, v3 - h3);
            __nv_bfloat16* row = dst + ((size_t)bh * T_ + t0 + r) * 256;
            *(uint2*)(row + c4)       = hp;
            *(uint2*)(row + 128 + c4) = lp;
        }
        __syncthreads();
    }
}

// ===================== tensor-core flash attention ==========================
// Block: 128 q-rows (8 warps x 16 rows, warp-local softmax), k-tiles of 64.
// S = Qh*Kh + Ql*Kh + Qh*Kl ; O += Ph*Vh + Pl*Vh + Ph*Vl  (all fp32 accum).
#define APITCH 136           // bf16 elems/row (272 B) -> conflict-free LDSM
#define OPITCH 132
#define SQH 0
#define SQL 34816
#define SKH 69632
#define SKL 87040
#define SVH 104448
#define SVL 121856
#define SOST 69632           // O staging reuses K/V region
#define ATTN_SMEM 139264

__global__ __launch_bounds__(256, 1)
void attention_tc(const __nv_bfloat16* __restrict__ q2,
                  const __nv_bfloat16* __restrict__ k2,
                  const __nv_bfloat16* __restrict__ v2,
                  __nv_bfloat16* __restrict__ y2)
{
    extern __shared__ char sm[];
    const uint32_t sb = smem_u32(sm);
    const int bid  = blockIdx.x;
    const int qblk = bid & 3;
    const int h    = (bid >> 2) & 15;
    const int b    = bid >> 6;
    const int bh   = b * H_ + h;
    const int q0   = qblk << 7;
    const int tid  = threadIdx.x;
    const int w    = tid >> 5, lane = tid & 31;
    const int gid  = lane >> 2, tig = lane & 3;
    const int l15  = lane & 15;
    const int acg  = (lane >> 4) & 1;
    const int l7   = lane & 7;
    const int bcg  = (lane >> 3) & 1;
    const float scale = 0.088388347648318447f;   // 1/sqrt(128)

    // ---- load Q tile (128 rows x 512B) into QH/QL
    {
        const char* src = (const char*)(q2 + ((size_t)bh * T_ + q0) * 256);
#pragma unroll
        for (int p = 0; p < 16; p++) {
            const int idx = tid + (p << 8);
            const int r = idx >> 5, seg = idx & 31;
            const uint4 v = *(const uint4*)(src + (size_t)r * 512 + seg * 16);
            const int off = (r * APITCH + (seg & 15) * 8) * 2;
            *(uint4*)(sm + ((seg < 16) ? SQH : SQL) + off) = v;
        }
    }

    float m0r = -INFINITY, m1r = -INFINITY, l0 = 0.0f, l1 = 0.0f;
    float oacc[16][4];
#pragma unroll
    for (int nt = 0; nt < 16; nt++)
#pragma unroll
        for (int i = 0; i < 4; i++) oacc[nt][i] = 0.0f;

    const uint32_t arow2 = (uint32_t)(((w << 4) + l15) * APITCH) * 2;

    const int nkt = (qblk << 1) + 2;
    for (int kt = 0; kt < nkt; kt++) {
        const int c0 = kt << 6;
        __syncthreads();   // previous compute done before K/V overwrite
        {
            const char* ks = (const char*)(k2 + ((size_t)bh * T_ + c0) * 256);
            const char* vs = (const char*)(v2 + ((size_t)bh * T_ + c0) * 256);
#pragma unroll
            for (int p = 0; p < 8; p++) {
                const int idx = tid + (p << 8);
                const int r = idx >> 5, seg = idx & 31;
                const uint4 kv = *(const uint4*)(ks + (size_t)r * 512 + seg * 16);
                const uint4 vv = *(const uint4*)(vs + (size_t)r * 512 + seg * 16);
                const int off = (r * APITCH + (seg & 15) * 8) * 2;
                if (seg < 16) { *(uint4*)(sm + SKH + off) = kv; *(uint4*)(sm + SVH + off) = vv; }
                else          { *(uint4*)(sm + SKL + off) = kv; *(uint4*)(sm + SVL + off) = vv; }
            }
        }
        __syncthreads();   // tiles ready (covers Q load on iter 0)

        const bool skip = (q0 + (w << 4) + 15) < c0;   // warp fully masked
        if (!skip) {
            // ---- S = scale * Q K^T over split parts
            float sacc[8][4];
#pragma unroll
            for (int nt = 0; nt < 8; nt++)
#pragma unroll
                for (int i = 0; i < 4; i++) sacc[nt][i] = 0.0f;

#pragma unroll
            for (int j = 0; j < 8; j++) {
                const uint32_t ka = (uint32_t)(j * 32 + acg * 16);
                const uint32_t kb = (uint32_t)(j * 32 + bcg * 16);
                uint32_t ah[4], alr[4];
                LDX4(ah,  sb + SQH + arow2 + ka);
                LDX4(alr, sb + SQL + arow2 + ka);
#pragma unroll
                for (int nt = 0; nt < 8; nt++) {
                    uint32_t bb[2];
                    LDX2(bb, sb + SKH + (uint32_t)(((nt << 3) + l7) * APITCH) * 2 + kb);
                    MMA16816(sacc[nt], ah,  bb);
                    MMA16816(sacc[nt], alr, bb);
                }
            }
#pragma unroll
            for (int j = 0; j < 8; j++) {
                const uint32_t ka = (uint32_t)(j * 32 + acg * 16);
                const uint32_t kb = (uint32_t)(j * 32 + bcg * 16);
                uint32_t ah[4];
                LDX4(ah, sb + SQH + arow2 + ka);
#pragma unroll
                for (int nt = 0; nt < 8; nt++) {
                    uint32_t bb[2];
                    LDX2(bb, sb + SKL + (uint32_t)(((nt << 3) + l7) * APITCH) * 2 + kb);
                    MMA16816(sacc[nt], ah, bb);
                }
            }

            // ---- mask + online softmax (warp-local, rows gid & gid+8)
            const int r0g = q0 + (w << 4) + gid;
            const int r1g = r0g + 8;
            float mx0 = -INFINITY, mx1 = -INFINITY;
#pragma unroll
            for (int nt = 0; nt < 8; nt++) {
                const int cb = c0 + (nt << 3) + (tig << 1);
#pragma unroll
                for (int e = 0; e < 2; e++) {
                    float s0 = sacc[nt][e] * scale;
                    if (cb + e > r0g) s0 = -INFINITY;
                    sacc[nt][e] = s0; mx0 = fmaxf(mx0, s0);
                    float s1 = sacc[nt][2 + e] * scale;
                    if (cb + e > r1g) s1 = -INFINITY;
                    sacc[nt][2 + e] = s1; mx1 = fmaxf(mx1, s1);
                }
            }
            mx0 = fmaxf(mx0, __shfl_xor_sync(0xffffffffu, mx0, 1));
            mx0 = fmaxf(mx0, __shfl_xor_sync(0xffffffffu, mx0, 2));
            mx1 = fmaxf(mx1, __shfl_xor_sync(0xffffffffu, mx1, 1));
            mx1 = fmaxf(mx1, __shfl_xor_sync(0xffffffffu, mx1, 2));
            const float mn0 = fmaxf(m0r, mx0), mn1 = fmaxf(m1r, mx1);
            const float al0 = __expf(m0r - mn0), al1 = __expf(m1r - mn1);
            m0r = mn0; m1r = mn1;
            float sum0 = 0.0f, sum1 = 0.0f;
#pragma unroll
            for (int nt = 0; nt < 8; nt++) {
#pragma unroll
                for (int e = 0; e < 2; e++) {
                    const float p0 = __expf(sacc[nt][e] - mn0);
                    sacc[nt][e] = p0; sum0 += p0;
                    const float p1 = __expf(sacc[nt][2 + e] - mn1);
                    sacc[nt][2 + e] = p1; sum1 += p1;
                }
            }
            sum0 += __shfl_xor_sync(0xffffffffu, sum0, 1);
            sum0 += __shfl_xor_sync(0xffffffffu, sum0, 2);
            sum1 += __shfl_xor_sync(0xffffffffu, sum1, 1);
            sum1 += __shfl_xor_sync(0xffffffffu, sum1, 2);
            l0 = l0 * al0 + sum0;
            l1 = l1 * al1 + sum1;
#pragma unroll
            for (int nt = 0; nt < 16; nt++) {
                oacc[nt][0] *= al0; oacc[nt][1] *= al0;
                oacc[nt][2] *= al1; oacc[nt][3] *= al1;
            }

            // ---- P -> A fragments (hi + lo), in registers
            uint32_t ph[4][4], pl[4][4];
#pragma unroll
            for (int j = 0; j < 4; j++) {
                const float* s0 = sacc[2 * j];
                const float* s1 = sacc[2 * j + 1];
                const float h00 = bf16_round(s0[0]), h01 = bf16_round(s0[1]);
                const float h02 = bf16_round(s0[2]), h03 = bf16_round(s0[3]);
                const float h10 = bf16_round(s1[0]), h11 = bf16_round(s1[1]);
                const float h12 = bf16_round(s1[2]), h13 = bf16_round(s1[3]);
                ph[j][0] = pack2(h00, h01);
                ph[j][1] = pack2(h02, h03);
                ph[j][2] = pack2(h10, h11);
                ph[j][3] = pack2(h12, h13);
                pl[j][0] = pack2(s0[0] - h00, s0[1] - h01);
                pl[j][1] = pack2(s0[2] - h02, s0[3] - h03);
                pl[j][2] = pack2(s1[0] - h10, s1[1] - h11);
                pl[j][3] = pack2(s1[2] - h12, s1[3] - h13);
            }

            // ---- O += P @ V (3-split)
#pragma unroll
            for (int j = 0; j < 4; j++) {
                const uint32_t va = (uint32_t)(((j << 4) + l15) * APITCH) * 2;
#pragma unroll
                for (int nt = 0; nt < 16; nt++) {
                    uint32_t bhv[2], blv[2];
                    LDX2T(bhv, sb + SVH + va + (uint32_t)(nt << 4));
                    LDX2T(blv, sb + SVL + va + (uint32_t)(nt << 4));
                    MMA16816(oacc[nt], ph[j], bhv);
                    MMA16816(oacc[nt], pl[j], bhv);
                    MMA16816(oacc[nt], ph[j], blv);
                }
            }
        }
    }
    __syncthreads();   // all compute done before O staging overwrites K/V smem

    // ---- normalize + stage O in smem (reuse K/V region)
    {
        float* Ost = (float*)(sm + SOST);
        const float iv0 = 1.0f / l0, iv1 = 1.0f / l1;
        const int rl0 = (w << 4) + gid, rl1 = rl0 + 8;
#pragma unroll
        for (int nt = 0; nt < 16; nt++) {
            const int cc = (nt << 3) + (tig << 1);
            Ost[rl0 * OPITCH + cc]     = oacc[nt][0] * iv0;
            Ost[rl0 * OPITCH + cc + 1] = oacc[nt][1] * iv0;
            Ost[rl1 * OPITCH + cc]     = oacc[nt][2] * iv1;
            Ost[rl1 * OPITCH + cc + 1] = oacc[nt][3] * iv1;
        }
    }
    __syncthreads();

    // ---- write y2 hi/lo split [M, 6144]
    {
        const float* Ost = (const float*)(sm + SOST);
        const int kcb = h * HD_;
#pragma unroll
        for (int p = 0; p < 16; p++) {
            const int idx = tid + (p << 8);
            const int r = idx >> 5, c4 = (idx & 31) << 2;
            const float v0 = Ost[r * OPITCH + c4],     v1 = Ost[r * OPITCH + c4 + 1];
            const float v2f = Ost[r * OPITCH + c4 + 2], v3 = Ost[r * OPITCH + c4 + 3];
            const float h0 = bf16_round(v0), h1 = bf16_round(v1);
            const float h2 = bf16_round(v2f), h3 = bf16_round(v3);
            uint2 hp, lp;
            hp.x = pack2(h0, h1); hp.y = pack2(h2, h3);
            lp.x = pack2(v0 - h0, v1 - h1); lp.y = pack2(v2f - h2, v3 - h3);
            const size_t ro = (size_t)(b * T_ + q0 + r) * K3_;
            *(uint2*)&y2[ro + kcb + c4]        = hp;
            *(uint2*)&y2[ro + 2048 + kcb + c4] = lp;
            *(uint2*)&y2[ro + 4096 + kcb + c4] = hp;
        }
    }
}

// ---------------------------------------------------------------------------
extern "C" void kernel_launch(void* const* d_in, const int* in_sizes, int n_in,
                              void* d_out, int out_size)
{
    const float* x    = (const float*)d_in[0];   // [16,512,2048]
    const float* Wqkv = (const float*)d_in[1];   // [2048,6144]
    const float* Wout = (const float*)d_in[2];   // [2048,2048]
    float* out = (float*)d_out;                  // [16,512,2048]

    float *qkv;
    __nv_bfloat16 *q2, *k2, *v2, *a2, *b2q, *b2o, *y2;
    cudaGetSymbolAddress((void**)&qkv, g_qkv);
    cudaGetSymbolAddress((void**)&q2,  g_q2);
    cudaGetSymbolAddress((void**)&k2,  g_k2);
    cudaGetSymbolAddress((void**)&v2,  g_v2);
    cudaGetSymbolAddress((void**)&a2,  g_a2);
    cudaGetSymbolAddress((void**)&b2q, g_b2q);
    cudaGetSymbolAddress((void**)&b2o, g_b2o);
    cudaGetSymbolAddress((void**)&y2,  g_y2);

    // 0) bf16 hi/lo conversions
    conv_a_kernel<<<(M_ * C_) / 1024, 256>>>(x, a2);
    conv_w_kernel<<<dim3(N3_ / 32, C_ / 32), 256>>>(Wqkv, b2q, N3_);
    conv_w_kernel<<<dim3(C_ / 32,  C_ / 32), 256>>>(Wout, b2o, C_);

    cudaFuncSetAttribute(gemm_mma, cudaFuncAttributeMaxDynamicSharedMemorySize, G_SMEM_BYTES);

    // 1) qkv = x @ Wqkv   (mma.sync bf16 3-split, 256x128 tiles)
    gemm_mma<<<dim3(N3_ / 128, M_ / 256), 512, G_SMEM_BYTES>>>(a2, b2q, qkv, N3_);

    // 2) RoPE + split q,k,v -> bf16 hi/lo [B,H,T,256]
    rope_split_kernel<<<B_ * H_ * (T_ / 64), 256>>>(qkv, q2, k2, v2);

    // 3) tensor-core causal flash attention -> y2 (split layout)
    cudaFuncSetAttribute(attention_tc, cudaFuncAttributeMaxDynamicSharedMemorySize, ATTN_SMEM);
    attention_tc<<<B_ * H_ * 4, 256, ATTN_SMEM>>>(q2, k2, v2, y2);

    // 4) out = y @ Wout   (mma.sync bf16 3-split)
    gemm_mma<<<dim3(C_ / 128, M_ / 256), 512, G_SMEM_BYTES>>>(y2, b2o, out, C_);
}

// round 14
// speedup vs baseline: 1.1232x; 1.1232x over previous
#include <cuda_runtime.h>
#include <cuda_bf16.h>
#include <math.h>
#include <stdint.h>

// Problem dims
#define B_   16
#define T_   512
#define C_   2048
#define H_   16
#define HD_  128
#define N3_  6144   // 3*C
#define M_   8192   // B*T
#define K3_  6144   // split-K (hi|lo|hi concatenation) for both GEMMs
#define KC_  64
#define NT_  (K3_ / KC_)

// ---------------- scratch (device globals; no runtime allocation) ----------
__device__ __nv_bfloat16  g_q2   [(size_t)B_ * H_ * T_ * 256];  // [B,H,T, hi128|lo128]
__device__ __nv_bfloat16  g_k2   [(size_t)B_ * H_ * T_ * 256];
__device__ __nv_bfloat16  g_v2   [(size_t)B_ * H_ * T_ * 256];
__device__ __nv_bfloat16  g_a2   [(size_t)M_ * K3_];            // [M, 3K] = [x_hi | x_lo | x_hi]
__device__ __nv_bfloat16  g_b2q  [(size_t)N3_ * K3_];           // [6144, 3K] = [W_hi | W_hi | W_lo]
__device__ __nv_bfloat16  g_b2o  [(size_t)C_ * K3_];            // [2048, 3K]
__device__ __nv_bfloat16  g_y2   [(size_t)M_ * K3_];            // attention out, split layout

// ===================== helpers ==============================================
__device__ __forceinline__ uint32_t smem_u32(const void* p) {
    uint32_t a;
    asm("{ .reg .u64 t; cvta.to.shared.u64 t, %1; cvt.u32.u64 %0, t; }" : "=r"(a) : "l"(p));
    return a;
}
__device__ __forceinline__ void cp16(uint32_t dst, const void* src) {
    asm volatile("cp.async.cg.shared.global [%0], [%1], 16;" :: "r"(dst), "l"(src));
}
#define CP_COMMIT()  asm volatile("cp.async.commit_group;" ::: "memory")
#define CP_WAIT1()   asm volatile("cp.async.wait_group 1;" ::: "memory")
#define SW128(off) ((off) ^ (((off) >> 3) & 0x70))

#define LDX4(a, addr) asm volatile( \
    "ldmatrix.sync.aligned.m8n8.x4.shared.b16 {%0,%1,%2,%3}, [%4];" \
    : "=r"((a)[0]), "=r"((a)[1]), "=r"((a)[2]), "=r"((a)[3]) : "r"(addr))
#define LDX2(bq, addr) asm volatile( \
    "ldmatrix.sync.aligned.m8n8.x2.shared.b16 {%0,%1}, [%2];" \
    : "=r"((bq)[0]), "=r"((bq)[1]) : "r"(addr))
#define LDX2T(bq, addr) asm volatile( \
    "ldmatrix.sync.aligned.m8n8.x2.trans.shared.b16 {%0,%1}, [%2];" \
    : "=r"((bq)[0]), "=r"((bq)[1]) : "r"(addr))
#define MMA16816(c, a, bq) asm volatile( \
    "mma.sync.aligned.m16n8k16.row.col.f32.bf16.bf16.f32 " \
    "{%0,%1,%2,%3}, {%4,%5,%6,%7}, {%8,%9}, {%0,%1,%2,%3};" \
    : "+f"((c)[0]), "+f"((c)[1]), "+f"((c)[2]), "+f"((c)[3]) \
    : "r"((a)[0]), "r"((a)[1]), "r"((a)[2]), "r"((a)[3]), "r"((bq)[0]), "r"((bq)[1]))

__device__ __forceinline__ uint32_t pack2(float a, float b) {
    __nv_bfloat162 t = __floats2bfloat162_rn(a, b);
    return *reinterpret_cast<uint32_t*>(&t);
}
__device__ __forceinline__ float bf16_round(float a) {
    return __bfloat162float(__float2bfloat16(a));
}

// ===================== conversion kernels ===================================
__global__ void conv_a_kernel(const float* __restrict__ X, __nv_bfloat16* __restrict__ A2)
{
    const int idx = blockIdx.x * 256 + threadIdx.x;
    const int e = idx << 2;
    const int m = e >> 11;
    const int k = e & 2047;
    const float4 v = *(const float4*)&X[(size_t)e];
    const float h0 = bf16_round(v.x), h1 = bf16_round(v.y);
    const float h2 = bf16_round(v.z), h3 = bf16_round(v.w);
    uint2 hp, lp;
    hp.x = pack2(h0, h1); hp.y = pack2(h2, h3);
    lp.x = pack2(v.x - h0, v.y - h1); lp.y = pack2(v.z - h2, v.w - h3);
    const size_t ro = (size_t)m * K3_;
    *(uint2*)&A2[ro + k]        = hp;
    *(uint2*)&A2[ro + 2048 + k] = lp;
    *(uint2*)&A2[ro + 4096 + k] = hp;
}

__global__ void conv_w_kernel(const float* __restrict__ W, __nv_bfloat16* __restrict__ B2, int N)
{
    __shared__ float tile[32][33];
    const int n0 = blockIdx.x << 5;
    const int k0 = blockIdx.y << 5;
    const int tid = threadIdx.x;
    const int c = tid & 31, rb = tid >> 5;
#pragma unroll
    for (int j = 0; j < 4; j++) {
        const int r = rb + (j << 3);
        tile[r][c] = W[(size_t)(k0 + r) * N + n0 + c];
    }
    __syncthreads();
#pragma unroll
    for (int j = 0; j < 4; j++) {
        const int nl = rb + (j << 3);
        const int kl = c;
        const float v = tile[kl][nl];
        const float h = bf16_round(v);
        const __nv_bfloat16 hb = __float2bfloat16(h);
        const __nv_bfloat16 lb = __float2bfloat16(v - h);
        const size_t ro = (size_t)(n0 + nl) * K3_ + k0 + kl;
        B2[ro]        = hb;
        B2[ro + 2048] = hb;
        B2[ro + 4096] = lb;
    }
}

// ===================== shared GEMM mainloop (R12 config) ====================
// 128x128 CTA tile, 256 threads (8 warps, 2x4), warp tile 64x32,
// K-chunk 64, 3-stage cp.async pipeline, 2 CTAs/SM.
#define G_SMEM_BYTES (3 * 32768)

#define GEMM_MAINLOOP(A, Bt)                                                  \
    extern __shared__ char sm[];                                              \
    const uint32_t sbase = smem_u32(sm);                                      \
    const int tid  = threadIdx.x;                                             \
    const int lane = tid & 31;                                                \
    const int w    = tid >> 5;                                                \
    const int wm   = w >> 2;                                                  \
    const int wn   = w & 3;                                                   \
    const int m0 = blockIdx.y << 7;                                           \
    const int n0 = blockIdx.x << 7;                                           \
    const int r0  = tid >> 3;                                                 \
    const int c16 = tid & 7;                                                  \
    const uint32_t dsw = SW128((uint32_t)(r0 * 128 + c16 * 16));              \
    const char* Ag = (const char*)((A)  + (size_t)(m0 + r0) * K3_) + c16 * 16;\
    const char* Bg = (const char*)((Bt) + (size_t)(n0 + r0) * K3_) + c16 * 16;\
    const size_t rstep = (size_t)32 * K3_ * 2;                                \
    const int l15 = lane & 15;                                                \
    const int acg = (lane >> 4) & 1;                                          \
    const int l7  = lane & 7;                                                 \
    const int bcg = (lane >> 3) & 1;                                          \
    const uint32_t xrA = (uint32_t)((l15 & 7) << 4);                          \
    const uint32_t xrB = (uint32_t)(l7 << 4);                                 \
    uint32_t baseA[4], baseB[4];                                              \
    _Pragma("unroll")                                                         \
    for (int mt = 0; mt < 4; mt++)                                            \
        baseA[mt] = (uint32_t)((wm * 64 + mt * 16 + l15) * 128);              \
    _Pragma("unroll")                                                         \
    for (int nt = 0; nt < 4; nt++)                                            \
        baseB[nt] = (uint32_t)(16384 + (wn * 32 + nt * 8 + l7) * 128);        \
    float acc[4][4][4];                                                       \
    _Pragma("unroll")                                                         \
    for (int mt = 0; mt < 4; mt++)                                            \
        _Pragma("unroll")                                                     \
        for (int nt = 0; nt < 4; nt++)                                        \
            _Pragma("unroll")                                                 \
            for (int i = 0; i < 4; i++) acc[mt][nt][i] = 0.0f;                \
    _Pragma("unroll")                                                         \
    for (int pt = 0; pt < 2; pt++) {                                          \
        const uint32_t so = (uint32_t)pt * 32768u;                            \
        const char* ga = Ag + (size_t)pt * 128;                               \
        const char* gb = Bg + (size_t)pt * 128;                               \
        _Pragma("unroll")                                                     \
        for (int i = 0; i < 4; i++) {                                         \
            cp16(sbase + so + dsw + i * 4096,          ga + (size_t)i * rstep);\
            cp16(sbase + so + 16384 + dsw + i * 4096,  gb + (size_t)i * rstep);\
        }                                                                     \
        CP_COMMIT();                                                          \
    }                                                                         \
    int buf = 0, nbuf = 2;                                                    \
    for (int t = 0; t < NT_; t++) {                                           \
        CP_WAIT1();                                                           \
        __syncthreads();                                                      \
        {                                                                     \
            if (t + 2 < NT_) {                                                \
                const uint32_t so = (uint32_t)nbuf * 32768u;                  \
                const char* ga = Ag + (size_t)(t + 2) * 128;                  \
                const char* gb = Bg + (size_t)(t + 2) * 128;                  \
                _Pragma("unroll")                                             \
                for (int i = 0; i < 4; i++) {                                 \
                    cp16(sbase + so + dsw + i * 4096,          ga + (size_t)i * rstep);\
                    cp16(sbase + so + 16384 + dsw + i * 4096,  gb + (size_t)i * rstep);\
                }                                                             \
            }                                                                 \
            CP_COMMIT();                                                      \
        }                                                                     \
        const uint32_t bufo = sbase + (uint32_t)buf * 32768u;                 \
        _Pragma("unroll")                                                     \
        for (int ks = 0; ks < 4; ks++) {                                      \
            const uint32_t axo = ((uint32_t)(ks * 32 + acg * 16)) ^ xrA;      \
            const uint32_t bxo = ((uint32_t)(ks * 32 + bcg * 16)) ^ xrB;      \
            uint32_t a[4][4], b[4][2];                                        \
            _Pragma("unroll")                                                 \
            for (int mt = 0; mt < 4; mt++)                                    \
                LDX4(a[mt], bufo + baseA[mt] + axo);                          \
            _Pragma("unroll")                                                 \
            for (int nt = 0; nt < 4; nt++)                                    \
                LDX2(b[nt], bufo + baseB[nt] + bxo);                          \
            _Pragma("unroll")                                                 \
            for (int mt = 0; mt < 4; mt++)                                    \
                _Pragma("unroll")                                             \
                for (int nt = 0; nt < 4; nt++)                                \
                    MMA16816(acc[mt][nt], a[mt], b[nt]);                      \
        }                                                                     \
        buf  = (buf  == 2) ? 0 : buf + 1;                                     \
        nbuf = (nbuf == 2) ? 0 : nbuf + 1;                                    \
    }

// ---- out-projection GEMM: plain fp32 C writeback ---------------------------
__global__ __launch_bounds__(256, 2)
void gemm_mma(const __nv_bfloat16* __restrict__ A,
              const __nv_bfloat16* __restrict__ Bt,
              float* __restrict__ C, int N)
{
    GEMM_MAINLOOP(A, Bt)

    const int gid = lane >> 2, tig = lane & 3;
#pragma unroll
    for (int mt = 0; mt < 4; mt++) {
        const int r = m0 + wm * 64 + mt * 16 + gid;
#pragma unroll
        for (int nt = 0; nt < 4; nt++) {
            const int cc = n0 + wn * 32 + nt * 8 + 2 * tig;
            float2 v0 = make_float2(acc[mt][nt][0], acc[mt][nt][1]);
            float2 v1 = make_float2(acc[mt][nt][2], acc[mt][nt][3]);
            *(float2*)&C[(size_t)r * N + cc]       = v0;
            *(float2*)&C[(size_t)(r + 8) * N + cc] = v1;
        }
    }
}

// ---- QKV GEMM with fused RoPE + hi/lo split epilogue ----------------------
// n-tile blockIdx.x = (which, h): col c = which*2048 + h*128 + d.
// RoPE pairs (d, d+8), d<8 are thread-local: acc[mt][0][e] (col 2tig+e) and
// acc[mt][1][e] (col 8+2tig+e) in warp wn==0. Rotation in fp32, then split.
__global__ __launch_bounds__(256, 2)
void gemm_qkv(const __nv_bfloat16* __restrict__ A,
              const __nv_bfloat16* __restrict__ Bt,
              __nv_bfloat16* __restrict__ q2,
              __nv_bfloat16* __restrict__ k2,
              __nv_bfloat16* __restrict__ v2)
{
    GEMM_MAINLOOP(A, Bt)

    const int gid = lane >> 2, tig = lane & 3;
    const int nblk  = blockIdx.x;
    const int which = nblk >> 4;
    const int h     = nblk & 15;
    __nv_bfloat16* dst = (which == 0) ? q2 : (which == 1) ? k2 : v2;

#pragma unroll
    for (int mt = 0; mt < 4; mt++) {
        const int r0g = m0 + wm * 64 + mt * 16 + gid;
        const int r1g = r0g + 8;
        const int t0v = r0g & 511, t1v = r1g & 511;
        if (which < 2 && wn == 0) {
#pragma unroll
            for (int e = 0; e < 2; e++) {
                const int d = 2 * tig + e;
                const float inv = powf(10000.0f, -(float)d * 0.125f);
                float sn0, cs0, sn1, cs1;
                sincosf((float)t0v * inv, &sn0, &cs0);
                sincosf((float)t1v * inv, &sn1, &cs1);
                float x1 = acc[mt][0][e], x2 = acc[mt][1][e];
                acc[mt][0][e] = x1 * cs0 - x2 * sn0;
                acc[mt][1][e] = x2 * cs0 + x1 * sn0;
                x1 = acc[mt][0][2 + e]; x2 = acc[mt][1][2 + e];
                acc[mt][0][2 + e] = x1 * cs1 - x2 * sn1;
                acc[mt][1][2 + e] = x2 * cs1 + x1 * sn1;
            }
        }
        const int bh = (r0g >> 9) * H_ + h;
        __nv_bfloat16* row0 = dst + ((size_t)bh * T_ + t0v) * 256;
        __nv_bfloat16* row1 = dst + ((size_t)bh * T_ + t1v) * 256;
#pragma unroll
        for (int nt = 0; nt < 4; nt++) {
            const int cc = wn * 32 + nt * 8 + 2 * tig;
            float v0 = acc[mt][nt][0], v1 = acc[mt][nt][1];
            float h0 = bf16_round(v0), h1 = bf16_round(v1);
            *(uint32_t*)(row0 + cc)       = pack2(h0, h1);
            *(uint32_t*)(row0 + 128 + cc) = pack2(v0 - h0, v1 - h1);
            v0 = acc[mt][nt][2]; v1 = acc[mt][nt][3];
            h0 = bf16_round(v0); h1 = bf16_round(v1);
            *(uint32_t*)(row1 + cc)       = pack2(h0, h1);
            *(uint32_t*)(row1 + 128 + cc) = pack2(v0 - h0, v1 - h1);
        }
    }
}

// ===================== tensor-core flash attention ==========================
// Block: 128 q-rows (8 warps x 16 rows, warp-local softmax), k-tiles of 64.
// S = Qh*Kh + Ql*Kh + Qh*Kl ; O += Ph*Vh + Pl*Vh + Ph*Vl  (all fp32 accum).
#define APITCH 136           // bf16 elems/row (272 B) -> conflict-free LDSM
#define OPITCH 132
#define SQH 0
#define SQL 34816
#define SKH 69632
#define SKL 87040
#define SVH 104448
#define SVL 121856
#define SOST 69632           // O staging reuses K/V region
#define ATTN_SMEM 139264

__global__ __launch_bounds__(256, 1)
void attention_tc(const __nv_bfloat16* __restrict__ q2,
                  const __nv_bfloat16* __restrict__ k2,
                  const __nv_bfloat16* __restrict__ v2,
                  __nv_bfloat16* __restrict__ y2)
{
    extern __shared__ char sm[];
    const uint32_t sb = smem_u32(sm);
    const int bid  = blockIdx.x;
    const int qblk = bid & 3;
    const int h    = (bid >> 2) & 15;
    const int b    = bid >> 6;
    const int bh   = b * H_ + h;
    const int q0   = qblk << 7;
    const int tid  = threadIdx.x;
    const int w    = tid >> 5, lane = tid & 31;
    const int gid  = lane >> 2, tig = lane & 3;
    const int l15  = lane & 15;
    const int acg  = (lane >> 4) & 1;
    const int l7   = lane & 7;
    const int bcg  = (lane >> 3) & 1;
    const float scale = 0.088388347648318447f;   // 1/sqrt(128)

    // ---- load Q tile (128 rows x 512B) into QH/QL
    {
        const char* src = (const char*)(q2 + ((size_t)bh * T_ + q0) * 256);
#pragma unroll
        for (int p = 0; p < 16; p++) {
            const int idx = tid + (p << 8);
            const int r = idx >> 5, seg = idx & 31;
            const uint4 v = *(const uint4*)(src + (size_t)r * 512 + seg * 16);
            const int off = (r * APITCH + (seg & 15) * 8) * 2;
            *(uint4*)(sm + ((seg < 16) ? SQH : SQL) + off) = v;
        }
    }

    float m0r = -INFINITY, m1r = -INFINITY, l0 = 0.0f, l1 = 0.0f;
    float oacc[16][4];
#pragma unroll
    for (int nt = 0; nt < 16; nt++)
#pragma unroll
        for (int i = 0; i < 4; i++) oacc[nt][i] = 0.0f;

    const uint32_t arow2 = (uint32_t)(((w << 4) + l15) * APITCH) * 2;

    const int nkt = (qblk << 1) + 2;
    for (int kt = 0; kt < nkt; kt++) {
        const int c0 = kt << 6;
        __syncthreads();   // previous compute done before K/V overwrite
        {
            const char* ks = (const char*)(k2 + ((size_t)bh * T_ + c0) * 256);
            const char* vs = (const char*)(v2 + ((size_t)bh * T_ + c0) * 256);
#pragma unroll
            for (int p = 0; p < 8; p++) {
                const int idx = tid + (p << 8);
                const int r = idx >> 5, seg = idx & 31;
                const uint4 kv = *(const uint4*)(ks + (size_t)r * 512 + seg * 16);
                const uint4 vv = *(const uint4*)(vs + (size_t)r * 512 + seg * 16);
                const int off = (r * APITCH + (seg & 15) * 8) * 2;
                if (seg < 16) { *(uint4*)(sm + SKH + off) = kv; *(uint4*)(sm + SVH + off) = vv; }
                else          { *(uint4*)(sm + SKL + off) = kv; *(uint4*)(sm + SVL + off) = vv; }
            }
        }
        __syncthreads();   // tiles ready (covers Q load on iter 0)

        const bool skip = (q0 + (w << 4) + 15) < c0;   // warp fully masked
        if (!skip) {
            // ---- S = scale * Q K^T over split parts
            float sacc[8][4];
#pragma unroll
            for (int nt = 0; nt < 8; nt++)
#pragma unroll
                for (int i = 0; i < 4; i++) sacc[nt][i] = 0.0f;

#pragma unroll
            for (int j = 0; j < 8; j++) {
                const uint32_t ka = (uint32_t)(j * 32 + acg * 16);
                const uint32_t kb = (uint32_t)(j * 32 + bcg * 16);
                uint32_t ah[4], alr[4];
                LDX4(ah,  sb + SQH + arow2 + ka);
                LDX4(alr, sb + SQL + arow2 + ka);
#pragma unroll
                for (int nt = 0; nt < 8; nt++) {
                    uint32_t bb[2];
                    LDX2(bb, sb + SKH + (uint32_t)(((nt << 3) + l7) * APITCH) * 2 + kb);
                    MMA16816(sacc[nt], ah,  bb);
                    MMA16816(sacc[nt], alr, bb);
                }
            }
#pragma unroll
            for (int j = 0; j < 8; j++) {
                const uint32_t ka = (uint32_t)(j * 32 + acg * 16);
                const uint32_t kb = (uint32_t)(j * 32 + bcg * 16);
                uint32_t ah[4];
                LDX4(ah, sb + SQH + arow2 + ka);
#pragma unroll
                for (int nt = 0; nt < 8; nt++) {
                    uint32_t bb[2];
                    LDX2(bb, sb + SKL + (uint32_t)(((nt << 3) + l7) * APITCH) * 2 + kb);
                    MMA16816(sacc[nt], ah, bb);
                }
            }

            // ---- mask + online softmax (warp-local, rows gid & gid+8)
            const int r0g = q0 + (w << 4) + gid;
            const int r1g = r0g + 8;
            float mx0 = -INFINITY, mx1 = -INFINITY;
#pragma unroll
            for (int nt = 0; nt < 8; nt++) {
                const int cb = c0 + (nt << 3) + (tig << 1);
#pragma unroll
                for (int e = 0; e < 2; e++) {
                    float s0 = sacc[nt][e] * scale;
                    if (cb + e > r0g) s0 = -INFINITY;
                    sacc[nt][e] = s0; mx0 = fmaxf(mx0, s0);
                    float s1 = sacc[nt][2 + e] * scale;
                    if (cb + e > r1g) s1 = -INFINITY;
                    sacc[nt][2 + e] = s1; mx1 = fmaxf(mx1, s1);
                }
            }
            mx0 = fmaxf(mx0, __shfl_xor_sync(0xffffffffu, mx0, 1));
            mx0 = fmaxf(mx0, __shfl_xor_sync(0xffffffffu, mx0, 2));
            mx1 = fmaxf(mx1, __shfl_xor_sync(0xffffffffu, mx1, 1));
            mx1 = fmaxf(mx1, __shfl_xor_sync(0xffffffffu, mx1, 2));
            const float mn0 = fmaxf(m0r, mx0), mn1 = fmaxf(m1r, mx1);
            const float al0 = __expf(m0r - mn0), al1 = __expf(m1r - mn1);
            m0r = mn0; m1r = mn1;
            float sum0 = 0.0f, sum1 = 0.0f;
#pragma unroll
            for (int nt = 0; nt < 8; nt++) {
#pragma unroll
                for (int e = 0; e < 2; e++) {
                    const float p0 = __expf(sacc[nt][e] - mn0);
                    sacc[nt][e] = p0; sum0 += p0;
                    const float p1 = __expf(sacc[nt][2 + e] - mn1);
                    sacc[nt][2 + e] = p1; sum1 += p1;
                }
            }
            sum0 += __shfl_xor_sync(0xffffffffu, sum0, 1);
            sum0 += __shfl_xor_sync(0xffffffffu, sum0, 2);
            sum1 += __shfl_xor_sync(0xffffffffu, sum1, 1);
            sum1 += __shfl_xor_sync(0xffffffffu, sum1, 2);
            l0 = l0 * al0 + sum0;
            l1 = l1 * al1 + sum1;
#pragma unroll
            for (int nt = 0; nt < 16; nt++) {
                oacc[nt][0] *= al0; oacc[nt][1] *= al0;
                oacc[nt][2] *= al1; oacc[nt][3] *= al1;
            }

            // ---- P -> A fragments (hi + lo), in registers
            uint32_t ph[4][4], pl[4][4];
#pragma unroll
            for (int j = 0; j < 4; j++) {
                const float* s0 = sacc[2 * j];
                const float* s1 = sacc[2 * j + 1];
                const float h00 = bf16_round(s0[0]), h01 = bf16_round(s0[1]);
                const float h02 = bf16_round(s0[2]), h03 = bf16_round(s0[3]);
                const float h10 = bf16_round(s1[0]), h11 = bf16_round(s1[1]);
                const float h12 = bf16_round(s1[2]), h13 = bf16_round(s1[3]);
                ph[j][0] = pack2(h00, h01);
                ph[j][1] = pack2(h02, h03);
                ph[j][2] = pack2(h10, h11);
                ph[j][3] = pack2(h12, h13);
                pl[j][0] = pack2(s0[0] - h00, s0[1] - h01);
                pl[j][1] = pack2(s0[2] - h02, s0[3] - h03);
                pl[j][2] = pack2(s1[0] - h10, s1[1] - h11);
                pl[j][3] = pack2(s1[2] - h12, s1[3] - h13);
            }

            // ---- O += P @ V (3-split)
#pragma unroll
            for (int j = 0; j < 4; j++) {
                const uint32_t va = (uint32_t)(((j << 4) + l15) * APITCH) * 2;
#pragma unroll
                for (int nt = 0; nt < 16; nt++) {
                    uint32_t bhv[2], blv[2];
                    LDX2T(bhv, sb + SVH + va + (uint32_t)(nt << 4));
                    LDX2T(blv, sb + SVL + va + (uint32_t)(nt << 4));
                    MMA16816(oacc[nt], ph[j], bhv);
                    MMA16816(oacc[nt], pl[j], bhv);
                    MMA16816(oacc[nt], ph[j], blv);
                }
            }
        }
    }
    __syncthreads();   // all compute done before O staging overwrites K/V smem

    // ---- normalize + stage O in smem (reuse K/V region)
    {
        float* Ost = (float*)(sm + SOST);
        const float iv0 = 1.0f / l0, iv1 = 1.0f / l1;
        const int rl0 = (w << 4) + gid, rl1 = rl0 + 8;
#pragma unroll
        for (int nt = 0; nt < 16; nt++) {
            const int cc = (nt << 3) + (tig << 1);
            Ost[rl0 * OPITCH + cc]     = oacc[nt][0] * iv0;
            Ost[rl0 * OPITCH + cc + 1] = oacc[nt][1] * iv0;
            Ost[rl1 * OPITCH + cc]     = oacc[nt][2] * iv1;
            Ost[rl1 * OPITCH + cc + 1] = oacc[nt][3] * iv1;
        }
    }
    __syncthreads();

    // ---- write y2 hi/lo split [M, 6144]
    {
        const float* Ost = (const float*)(sm + SOST);
        const int kcb = h * HD_;
#pragma unroll
        for (int p = 0; p < 16; p++) {
            const int idx = tid + (p << 8);
            const int r = idx >> 5, c4 = (idx & 31) << 2;
            const float v0 = Ost[r * OPITCH + c4],     v1 = Ost[r * OPITCH + c4 + 1];
            const float v2f = Ost[r * OPITCH + c4 + 2], v3 = Ost[r * OPITCH + c4 + 3];
            const float h0 = bf16_round(v0), h1 = bf16_round(v1);
            const float h2 = bf16_round(v2f), h3 = bf16_round(v3);
            uint2 hp, lp;
            hp.x = pack2(h0, h1); hp.y = pack2(h2, h3);
            lp.x = pack2(v0 - h0, v1 - h1); lp.y = pack2(v2f - h2, v3 - h3);
            const size_t ro = (size_t)(b * T_ + q0 + r) * K3_;
            *(uint2*)&y2[ro + kcb + c4]        = hp;
            *(uint2*)&y2[ro + 2048 + kcb + c4] = lp;
            *(uint2*)&y2[ro + 4096 + kcb + c4] = hp;
        }
    }
}

// ---------------------------------------------------------------------------
extern "C" void kernel_launch(void* const* d_in, const int* in_sizes, int n_in,
                              void* d_out, int out_size)
{
    const float* x    = (const float*)d_in[0];   // [16,512,2048]
    const float* Wqkv = (const float*)d_in[1];   // [2048,6144]
    const float* Wout = (const float*)d_in[2];   // [2048,2048]
    float* out = (float*)d_out;                  // [16,512,2048]

    __nv_bfloat16 *q2, *k2, *v2, *a2, *b2q, *b2o, *y2;
    cudaGetSymbolAddress((void**)&q2,  g_q2);
    cudaGetSymbolAddress((void**)&k2,  g_k2);
    cudaGetSymbolAddress((void**)&v2,  g_v2);
    cudaGetSymbolAddress((void**)&a2,  g_a2);
    cudaGetSymbolAddress((void**)&b2q, g_b2q);
    cudaGetSymbolAddress((void**)&b2o, g_b2o);
    cudaGetSymbolAddress((void**)&y2,  g_y2);

    // 0) bf16 hi/lo conversions
    conv_a_kernel<<<(M_ * C_) / 1024, 256>>>(x, a2);
    conv_w_kernel<<<dim3(N3_ / 32, C_ / 32), 256>>>(Wqkv, b2q, N3_);
    conv_w_kernel<<<dim3(C_ / 32,  C_ / 32), 256>>>(Wout, b2o, C_);

    cudaFuncSetAttribute(gemm_qkv, cudaFuncAttributeMaxDynamicSharedMemorySize, G_SMEM_BYTES);
    cudaFuncSetAttribute(gemm_mma, cudaFuncAttributeMaxDynamicSharedMemorySize, G_SMEM_BYTES);

    // 1) q2/k2/v2 = rope(split(x @ Wqkv))  — fused epilogue, no fp32 qkv
    gemm_qkv<<<dim3(N3_ / 128, M_ / 128), 256, G_SMEM_BYTES>>>(a2, b2q, q2, k2, v2);

    // 2) tensor-core causal flash attention -> y2 (split layout)
    cudaFuncSetAttribute(attention_tc, cudaFuncAttributeMaxDynamicSharedMemorySize, ATTN_SMEM);
    attention_tc<<<B_ * H_ * 4, 256, ATTN_SMEM>>>(q2, k2, v2, y2);

    // 3) out = y @ Wout   (mma.sync bf16 3-split)
    gemm_mma<<<dim3(C_ / 128, M_ / 128), 256, G_SMEM_BYTES>>>(y2, b2o, out, C_);
}

// round 15
// speedup vs baseline: 1.1345x; 1.0100x over previous
#include <cuda_runtime.h>
#include <cuda_bf16.h>
#include <math.h>
#include <stdint.h>

// Problem dims
#define B_   16
#define T_   512
#define C_   2048
#define H_   16
#define HD_  128
#define N3_  6144   // 3*C
#define M_   8192   // B*T
#define K3_  6144   // split-K (hi|lo|hi concatenation) for both GEMMs
#define KC_  64
#define NT_  (K3_ / KC_)

// ---------------- scratch (device globals; no runtime allocation) ----------
__device__ __nv_bfloat16  g_q2   [(size_t)B_ * H_ * T_ * 256];  // [B,H,T, hi128|lo128]
__device__ __nv_bfloat16  g_k2   [(size_t)B_ * H_ * T_ * 256];
__device__ __nv_bfloat16  g_v2   [(size_t)B_ * H_ * T_ * 256];
__device__ __nv_bfloat16  g_a2   [(size_t)M_ * K3_];            // [M, 3K] = [x_hi | x_lo | x_hi]
__device__ __nv_bfloat16  g_b2q  [(size_t)N3_ * K3_];           // [6144, 3K] = [W_hi | W_hi | W_lo]
__device__ __nv_bfloat16  g_b2o  [(size_t)C_ * K3_];            // [2048, 3K]
__device__ __nv_bfloat16  g_y2   [(size_t)M_ * K3_];            // attention out, split layout

// ===================== helpers ==============================================
__device__ __forceinline__ uint32_t smem_u32(const void* p) {
    uint32_t a;
    asm("{ .reg .u64 t; cvta.to.shared.u64 t, %1; cvt.u32.u64 %0, t; }" : "=r"(a) : "l"(p));
    return a;
}
__device__ __forceinline__ void cp16(uint32_t dst, const void* src) {
    asm volatile("cp.async.cg.shared.global [%0], [%1], 16;" :: "r"(dst), "l"(src));
}
#define CP_COMMIT()  asm volatile("cp.async.commit_group;" ::: "memory")
#define CP_WAIT1()   asm volatile("cp.async.wait_group 1;" ::: "memory")
#define SW128(off) ((off) ^ (((off) >> 3) & 0x70))

#define LDX4(a, addr) asm volatile( \
    "ldmatrix.sync.aligned.m8n8.x4.shared.b16 {%0,%1,%2,%3}, [%4];" \
    : "=r"((a)[0]), "=r"((a)[1]), "=r"((a)[2]), "=r"((a)[3]) : "r"(addr))
#define LDX2(bq, addr) asm volatile( \
    "ldmatrix.sync.aligned.m8n8.x2.shared.b16 {%0,%1}, [%2];" \
    : "=r"((bq)[0]), "=r"((bq)[1]) : "r"(addr))
#define LDX2T(bq, addr) asm volatile( \
    "ldmatrix.sync.aligned.m8n8.x2.trans.shared.b16 {%0,%1}, [%2];" \
    : "=r"((bq)[0]), "=r"((bq)[1]) : "r"(addr))
#define MMA16816(c, a, bq) asm volatile( \
    "mma.sync.aligned.m16n8k16.row.col.f32.bf16.bf16.f32 " \
    "{%0,%1,%2,%3}, {%4,%5,%6,%7}, {%8,%9}, {%0,%1,%2,%3};" \
    : "+f"((c)[0]), "+f"((c)[1]), "+f"((c)[2]), "+f"((c)[3]) \
    : "r"((a)[0]), "r"((a)[1]), "r"((a)[2]), "r"((a)[3]), "r"((bq)[0]), "r"((bq)[1]))

__device__ __forceinline__ uint32_t pack2(float a, float b) {
    __nv_bfloat162 t = __floats2bfloat162_rn(a, b);
    return *reinterpret_cast<uint32_t*>(&t);
}
__device__ __forceinline__ float bf16_round(float a) {
    return __bfloat162float(__float2bfloat16(a));
}

// ===================== conversion kernels ===================================
__global__ void conv_a_kernel(const float* __restrict__ X, __nv_bfloat16* __restrict__ A2)
{
    const int idx = blockIdx.x * 256 + threadIdx.x;
    const int e = idx << 2;
    const int m = e >> 11;
    const int k = e & 2047;
    const float4 v = *(const float4*)&X[(size_t)e];
    const float h0 = bf16_round(v.x), h1 = bf16_round(v.y);
    const float h2 = bf16_round(v.z), h3 = bf16_round(v.w);
    uint2 hp, lp;
    hp.x = pack2(h0, h1); hp.y = pack2(h2, h3);
    lp.x = pack2(v.x - h0, v.y - h1); lp.y = pack2(v.z - h2, v.w - h3);
    const size_t ro = (size_t)m * K3_;
    *(uint2*)&A2[ro + k]        = hp;
    *(uint2*)&A2[ro + 2048 + k] = lp;
    *(uint2*)&A2[ro + 4096 + k] = hp;
}

__global__ void conv_w_kernel(const float* __restrict__ W, __nv_bfloat16* __restrict__ B2, int N)
{
    __shared__ float tile[32][33];
    const int n0 = blockIdx.x << 5;
    const int k0 = blockIdx.y << 5;
    const int tid = threadIdx.x;
    const int c = tid & 31, rb = tid >> 5;
#pragma unroll
    for (int j = 0; j < 4; j++) {
        const int r = rb + (j << 3);
        tile[r][c] = W[(size_t)(k0 + r) * N + n0 + c];
    }
    __syncthreads();
#pragma unroll
    for (int j = 0; j < 4; j++) {
        const int nl = rb + (j << 3);
        const int kl = c;
        const float v = tile[kl][nl];
        const float h = bf16_round(v);
        const __nv_bfloat16 hb = __float2bfloat16(h);
        const __nv_bfloat16 lb = __float2bfloat16(v - h);
        const size_t ro = (size_t)(n0 + nl) * K3_ + k0 + kl;
        B2[ro]        = hb;
        B2[ro + 2048] = hb;
        B2[ro + 4096] = lb;
    }
}

// ===================== shared GEMM mainloop (R12 config) ====================
// 128x128 CTA tile, 256 threads (8 warps, 2x4), warp tile 64x32,
// K-chunk 64, 3-stage cp.async pipeline, 2 CTAs/SM.
#define G_SMEM_BYTES (3 * 32768)

#define GEMM_MAINLOOP(A, Bt)                                                  \
    extern __shared__ char sm[];                                              \
    const uint32_t sbase = smem_u32(sm);                                      \
    const int tid  = threadIdx.x;                                             \
    const int lane = tid & 31;                                                \
    const int w    = tid >> 5;                                                \
    const int wm   = w >> 2;                                                  \
    const int wn   = w & 3;                                                   \
    const int m0 = blockIdx.y << 7;                                           \
    const int n0 = blockIdx.x << 7;                                           \
    const int r0  = tid >> 3;                                                 \
    const int c16 = tid & 7;                                                  \
    const uint32_t dsw = SW128((uint32_t)(r0 * 128 + c16 * 16));              \
    const char* Ag = (const char*)((A)  + (size_t)(m0 + r0) * K3_) + c16 * 16;\
    const char* Bg = (const char*)((Bt) + (size_t)(n0 + r0) * K3_) + c16 * 16;\
    const size_t rstep = (size_t)32 * K3_ * 2;                                \
    const int l15 = lane & 15;                                                \
    const int acg = (lane >> 4) & 1;                                          \
    const int l7  = lane & 7;                                                 \
    const int bcg = (lane >> 3) & 1;                                          \
    const uint32_t xrA = (uint32_t)((l15 & 7) << 4);                          \
    const uint32_t xrB = (uint32_t)(l7 << 4);                                 \
    uint32_t baseA[4], baseB[4];                                              \
    _Pragma("unroll")                                                         \
    for (int mt = 0; mt < 4; mt++)                                            \
        baseA[mt] = (uint32_t)((wm * 64 + mt * 16 + l15) * 128);              \
    _Pragma("unroll")                                                         \
    for (int nt = 0; nt < 4; nt++)                                            \
        baseB[nt] = (uint32_t)(16384 + (wn * 32 + nt * 8 + l7) * 128);        \
    float acc[4][4][4];                                                       \
    _Pragma("unroll")                                                         \
    for (int mt = 0; mt < 4; mt++)                                            \
        _Pragma("unroll")                                                     \
        for (int nt = 0; nt < 4; nt++)                                        \
            _Pragma("unroll")                                                 \
            for (int i = 0; i < 4; i++) acc[mt][nt][i] = 0.0f;                \
    _Pragma("unroll")                                                         \
    for (int pt = 0; pt < 2; pt++) {                                          \
        const uint32_t so = (uint32_t)pt * 32768u;                            \
        const char* ga = Ag + (size_t)pt * 128;                               \
        const char* gb = Bg + (size_t)pt * 128;                               \
        _Pragma("unroll")                                                     \
        for (int i = 0; i < 4; i++) {                                         \
            cp16(sbase + so + dsw + i * 4096,          ga + (size_t)i * rstep);\
            cp16(sbase + so + 16384 + dsw + i * 4096,  gb + (size_t)i * rstep);\
        }                                                                     \
        CP_COMMIT();                                                          \
    }                                                                         \
    int buf = 0, nbuf = 2;                                                    \
    for (int t = 0; t < NT_; t++) {                                           \
        CP_WAIT1();                                                           \
        __syncthreads();                                                      \
        {                                                                     \
            if (t + 2 < NT_) {                                                \
                const uint32_t so = (uint32_t)nbuf * 32768u;                  \
                const char* ga = Ag + (size_t)(t + 2) * 128;                  \
                const char* gb = Bg + (size_t)(t + 2) * 128;                  \
                _Pragma("unroll")                                             \
                for (int i = 0; i < 4; i++) {                                 \
                    cp16(sbase + so + dsw + i * 4096,          ga + (size_t)i * rstep);\
                    cp16(sbase + so + 16384 + dsw + i * 4096,  gb + (size_t)i * rstep);\
                }                                                             \
            }                                                                 \
            CP_COMMIT();                                                      \
        }                                                                     \
        const uint32_t bufo = sbase + (uint32_t)buf * 32768u;                 \
        _Pragma("unroll")                                                     \
        for (int ks = 0; ks < 4; ks++) {                                      \
            const uint32_t axo = ((uint32_t)(ks * 32 + acg * 16)) ^ xrA;      \
            const uint32_t bxo = ((uint32_t)(ks * 32 + bcg * 16)) ^ xrB;      \
            uint32_t a[4][4], b[4][2];                                        \
            _Pragma("unroll")                                                 \
            for (int mt = 0; mt < 4; mt++)                                    \
                LDX4(a[mt], bufo + baseA[mt] + axo);                          \
            _Pragma("unroll")                                                 \
            for (int nt = 0; nt < 4; nt++)                                    \
                LDX2(b[nt], bufo + baseB[nt] + bxo);                          \
            _Pragma("unroll")                                                 \
            for (int mt = 0; mt < 4; mt++)                                    \
                _Pragma("unroll")                                             \
                for (int nt = 0; nt < 4; nt++)                                \
                    MMA16816(acc[mt][nt], a[mt], b[nt]);                      \
        }                                                                     \
        buf  = (buf  == 2) ? 0 : buf + 1;                                     \
        nbuf = (nbuf == 2) ? 0 : nbuf + 1;                                    \
    }

// ---- out-projection GEMM: plain fp32 C writeback ---------------------------
__global__ __launch_bounds__(256, 2)
void gemm_mma(const __nv_bfloat16* __restrict__ A,
              const __nv_bfloat16* __restrict__ Bt,
              float* __restrict__ C, int N)
{
    GEMM_MAINLOOP(A, Bt)

    const int gid = lane >> 2, tig = lane & 3;
#pragma unroll
    for (int mt = 0; mt < 4; mt++) {
        const int r = m0 + wm * 64 + mt * 16 + gid;
#pragma unroll
        for (int nt = 0; nt < 4; nt++) {
            const int cc = n0 + wn * 32 + nt * 8 + 2 * tig;
            float2 v0 = make_float2(acc[mt][nt][0], acc[mt][nt][1]);
            float2 v1 = make_float2(acc[mt][nt][2], acc[mt][nt][3]);
            *(float2*)&C[(size_t)r * N + cc]       = v0;
            *(float2*)&C[(size_t)(r + 8) * N + cc] = v1;
        }
    }
}

// ---- QKV GEMM with fused RoPE + hi/lo split epilogue ----------------------
__global__ __launch_bounds__(256, 2)
void gemm_qkv(const __nv_bfloat16* __restrict__ A,
              const __nv_bfloat16* __restrict__ Bt,
              __nv_bfloat16* __restrict__ q2,
              __nv_bfloat16* __restrict__ k2,
              __nv_bfloat16* __restrict__ v2)
{
    GEMM_MAINLOOP(A, Bt)

    const int gid = lane >> 2, tig = lane & 3;
    const int nblk  = blockIdx.x;
    const int which = nblk >> 4;
    const int h     = nblk & 15;
    __nv_bfloat16* dst = (which == 0) ? q2 : (which == 1) ? k2 : v2;

#pragma unroll
    for (int mt = 0; mt < 4; mt++) {
        const int r0g = m0 + wm * 64 + mt * 16 + gid;
        const int r1g = r0g + 8;
        const int t0v = r0g & 511, t1v = r1g & 511;
        if (which < 2 && wn == 0) {
#pragma unroll
            for (int e = 0; e < 2; e++) {
                const int d = 2 * tig + e;
                const float inv = powf(10000.0f, -(float)d * 0.125f);
                float sn0, cs0, sn1, cs1;
                sincosf((float)t0v * inv, &sn0, &cs0);
                sincosf((float)t1v * inv, &sn1, &cs1);
                float x1 = acc[mt][0][e], x2 = acc[mt][1][e];
                acc[mt][0][e] = x1 * cs0 - x2 * sn0;
                acc[mt][1][e] = x2 * cs0 + x1 * sn0;
                x1 = acc[mt][0][2 + e]; x2 = acc[mt][1][2 + e];
                acc[mt][0][2 + e] = x1 * cs1 - x2 * sn1;
                acc[mt][1][2 + e] = x2 * cs1 + x1 * sn1;
            }
        }
        const int bh = (r0g >> 9) * H_ + h;
        __nv_bfloat16* row0 = dst + ((size_t)bh * T_ + t0v) * 256;
        __nv_bfloat16* row1 = dst + ((size_t)bh * T_ + t1v) * 256;
#pragma unroll
        for (int nt = 0; nt < 4; nt++) {
            const int cc = wn * 32 + nt * 8 + 2 * tig;
            float v0 = acc[mt][nt][0], v1 = acc[mt][nt][1];
            float h0 = bf16_round(v0), h1 = bf16_round(v1);
            *(uint32_t*)(row0 + cc)       = pack2(h0, h1);
            *(uint32_t*)(row0 + 128 + cc) = pack2(v0 - h0, v1 - h1);
            v0 = acc[mt][nt][2]; v1 = acc[mt][nt][3];
            h0 = bf16_round(v0); h1 = bf16_round(v1);
            *(uint32_t*)(row1 + cc)       = pack2(h0, h1);
            *(uint32_t*)(row1 + 128 + cc) = pack2(v0 - h0, v1 - h1);
        }
    }
}

// ===================== tensor-core flash attention ==========================
// Block: 128 q-rows (8 warps x 16 rows, warp-local softmax), k-tiles of 64,
// K/V double-buffered via cp.async (tile kt+1 prefetched during compute of kt).
// S = Qh*Kh + Ql*Kh + Qh*Kl ; O += Ph*Vh + Pl*Vh + Ph*Vl  (all fp32 accum).
#define APITCH 136           // bf16 elems/row (272 B) -> conflict-free LDSM
#define OPITCH 132
#define SQH 0
#define SQL 34816
#define SKV 69632            // K/V stages: stage s at SKV + s*ASTAGE
#define ASTAGE 69632         // per stage: KH 0, KL 17408, VH 34816, VL 52224
#define SOST 69632           // O staging reuses stage-0 K/V region
#define ATTN_SMEM (69632 + 2 * 69632)   // 208896

__global__ __launch_bounds__(256, 1)
void attention_tc(const __nv_bfloat16* __restrict__ q2,
                  const __nv_bfloat16* __restrict__ k2,
                  const __nv_bfloat16* __restrict__ v2,
                  __nv_bfloat16* __restrict__ y2)
{
    extern __shared__ char sm[];
    const uint32_t sb = smem_u32(sm);
    const int bid  = blockIdx.x;
    const int qblk = bid & 3;
    const int h    = (bid >> 2) & 15;
    const int b    = bid >> 6;
    const int bh   = b * H_ + h;
    const int q0   = qblk << 7;
    const int tid  = threadIdx.x;
    const int w    = tid >> 5, lane = tid & 31;
    const int gid  = lane >> 2, tig = lane & 3;
    const int l15  = lane & 15;
    const int acg  = (lane >> 4) & 1;
    const int l7   = lane & 7;
    const int bcg  = (lane >> 3) & 1;
    const float scale = 0.088388347648318447f;   // 1/sqrt(128)

    // per-thread K/V cp.async addressing (same for every tile)
    const int ldr  = tid >> 5;           // 0..7  base row
    const int lseg = tid & 31;           // 16B segment within 512B row
    const uint32_t kvoff = (uint32_t)(((lseg < 16) ? 0 : 17408)
                         + ((ldr * APITCH + (lseg & 15) * 8) * 2));
    const uint32_t rowstride = (uint32_t)(8 * APITCH * 2);   // 8 rows per p-step
    const char* kbase = (const char*)(k2 + (size_t)bh * T_ * 256) + lseg * 16;
    const char* vbase = (const char*)(v2 + (size_t)bh * T_ * 256) + lseg * 16;

    // ---- load Q tile (128 rows x 512B) into QH/QL (direct; once per block)
    {
        const char* src = (const char*)(q2 + ((size_t)bh * T_ + q0) * 256);
#pragma unroll
        for (int p = 0; p < 16; p++) {
            const int idx = tid + (p << 8);
            const int r = idx >> 5, seg = idx & 31;
            const uint4 v = *(const uint4*)(src + (size_t)r * 512 + seg * 16);
            const int off = (r * APITCH + (seg & 15) * 8) * 2;
            *(uint4*)(sm + ((seg < 16) ? SQH : SQL) + off) = v;
        }
    }

    float m0r = -INFINITY, m1r = -INFINITY, l0 = 0.0f, l1 = 0.0f;
    float oacc[16][4];
#pragma unroll
    for (int nt = 0; nt < 16; nt++)
#pragma unroll
        for (int i = 0; i < 4; i++) oacc[nt][i] = 0.0f;

    const uint32_t arow2 = (uint32_t)(((w << 4) + l15) * APITCH) * 2;
    const int nkt = (qblk << 1) + 2;

    // ---- prologue: issue tile 0 into stage 0
    {
        const uint32_t dst0 = sb + SKV + kvoff;
        const char* ks = kbase;                 // tile 0: rows 0..63
        const char* vs = vbase;
#pragma unroll
        for (int p = 0; p < 8; p++) {
            cp16(dst0 + p * rowstride,          ks + (size_t)(ldr + p * 8) * 512);
            cp16(dst0 + 34816 + p * rowstride,  vs + (size_t)(ldr + p * 8) * 512);
        }
        CP_COMMIT();   // pending = 1
    }

    for (int kt = 0; kt < nkt; kt++) {
        __syncthreads();   // all warps done with tile kt-1 -> buffer (kt+1)&1 free
        // issue tile kt+1 into alternate stage (empty commit on tail)
        if (kt + 1 < nkt) {
            const uint32_t dstn = sb + SKV + (uint32_t)((kt + 1) & 1) * ASTAGE + kvoff;
            const char* ks = kbase + (size_t)(kt + 1) * 64 * 512;
            const char* vs = vbase + (size_t)(kt + 1) * 64 * 512;
#pragma unroll
            for (int p = 0; p < 8; p++) {
                cp16(dstn + p * rowstride,          ks + (size_t)(ldr + p * 8) * 512);
                cp16(dstn + 34816 + p * rowstride,  vs + (size_t)(ldr + p * 8) * 512);
            }
        }
        CP_COMMIT();       // pending = 2
        CP_WAIT1();        // tile kt's group complete (issued one iteration ago)
        __syncthreads();   // visibility of tile kt to all warps (also covers Q on kt=0)

        const uint32_t stg = sb + SKV + (uint32_t)(kt & 1) * ASTAGE;
        const uint32_t SKHs = stg, SKLs = stg + 17408;
        const uint32_t SVHs = stg + 34816, SVLs = stg + 52224;
        const int c0 = kt << 6;

        const bool skip = (q0 + (w << 4) + 15) < c0;   // warp fully masked
        if (!skip) {
            // ---- S = scale * Q K^T over split parts
            float sacc[8][4];
#pragma unroll
            for (int nt = 0; nt < 8; nt++)
#pragma unroll
                for (int i = 0; i < 4; i++) sacc[nt][i] = 0.0f;

#pragma unroll
            for (int j = 0; j < 8; j++) {
                const uint32_t ka = (uint32_t)(j * 32 + acg * 16);
                const uint32_t kb = (uint32_t)(j * 32 + bcg * 16);
                uint32_t ah[4], alr[4];
                LDX4(ah,  sb + SQH + arow2 + ka);
                LDX4(alr, sb + SQL + arow2 + ka);
#pragma unroll
                for (int nt = 0; nt < 8; nt++) {
                    uint32_t bb[2];
                    LDX2(bb, SKHs + (uint32_t)(((nt << 3) + l7) * APITCH) * 2 + kb);
                    MMA16816(sacc[nt], ah,  bb);
                    MMA16816(sacc[nt], alr, bb);
                }
            }
#pragma unroll
            for (int j = 0; j < 8; j++) {
                const uint32_t ka = (uint32_t)(j * 32 + acg * 16);
                const uint32_t kb = (uint32_t)(j * 32 + bcg * 16);
                uint32_t ah[4];
                LDX4(ah, sb + SQH + arow2 + ka);
#pragma unroll
                for (int nt = 0; nt < 8; nt++) {
                    uint32_t bb[2];
                    LDX2(bb, SKLs + (uint32_t)(((nt << 3) + l7) * APITCH) * 2 + kb);
                    MMA16816(sacc[nt], ah, bb);
                }
            }

            // ---- mask + online softmax (warp-local, rows gid & gid+8)
            const int r0g = q0 + (w << 4) + gid;
            const int r1g = r0g + 8;
            float mx0 = -INFINITY, mx1 = -INFINITY;
#pragma unroll
            for (int nt = 0; nt < 8; nt++) {
                const int cb = c0 + (nt << 3) + (tig << 1);
#pragma unroll
                for (int e = 0; e < 2; e++) {
                    float s0 = sacc[nt][e] * scale;
                    if (cb + e > r0g) s0 = -INFINITY;
                    sacc[nt][e] = s0; mx0 = fmaxf(mx0, s0);
                    float s1 = sacc[nt][2 + e] * scale;
                    if (cb + e > r1g) s1 = -INFINITY;
                    sacc[nt][2 + e] = s1; mx1 = fmaxf(mx1, s1);
                }
            }
            mx0 = fmaxf(mx0, __shfl_xor_sync(0xffffffffu, mx0, 1));
            mx0 = fmaxf(mx0, __shfl_xor_sync(0xffffffffu, mx0, 2));
            mx1 = fmaxf(mx1, __shfl_xor_sync(0xffffffffu, mx1, 1));
            mx1 = fmaxf(mx1, __shfl_xor_sync(0xffffffffu, mx1, 2));
            const float mn0 = fmaxf(m0r, mx0), mn1 = fmaxf(m1r, mx1);
            const float al0 = __expf(m0r - mn0), al1 = __expf(m1r - mn1);
            m0r = mn0; m1r = mn1;
            float sum0 = 0.0f, sum1 = 0.0f;
#pragma unroll
            for (int nt = 0; nt < 8; nt++) {
#pragma unroll
                for (int e = 0; e < 2; e++) {
                    const float p0 = __expf(sacc[nt][e] - mn0);
                    sacc[nt][e] = p0; sum0 += p0;
                    const float p1 = __expf(sacc[nt][2 + e] - mn1);
                    sacc[nt][2 + e] = p1; sum1 += p1;
                }
            }
            sum0 += __shfl_xor_sync(0xffffffffu, sum0, 1);
            sum0 += __shfl_xor_sync(0xffffffffu, sum0, 2);
            sum1 += __shfl_xor_sync(0xffffffffu, sum1, 1);
            sum1 += __shfl_xor_sync(0xffffffffu, sum1, 2);
            l0 = l0 * al0 + sum0;
            l1 = l1 * al1 + sum1;
#pragma unroll
            for (int nt = 0; nt < 16; nt++) {
                oacc[nt][0] *= al0; oacc[nt][1] *= al0;
                oacc[nt][2] *= al1; oacc[nt][3] *= al1;
            }

            // ---- P -> A fragments (hi + lo), in registers
            uint32_t ph[4][4], pl[4][4];
#pragma unroll
            for (int j = 0; j < 4; j++) {
                const float* s0 = sacc[2 * j];
                const float* s1 = sacc[2 * j + 1];
                const float h00 = bf16_round(s0[0]), h01 = bf16_round(s0[1]);
                const float h02 = bf16_round(s0[2]), h03 = bf16_round(s0[3]);
                const float h10 = bf16_round(s1[0]), h11 = bf16_round(s1[1]);
                const float h12 = bf16_round(s1[2]), h13 = bf16_round(s1[3]);
                ph[j][0] = pack2(h00, h01);
                ph[j][1] = pack2(h02, h03);
                ph[j][2] = pack2(h10, h11);
                ph[j][3] = pack2(h12, h13);
                pl[j][0] = pack2(s0[0] - h00, s0[1] - h01);
                pl[j][1] = pack2(s0[2] - h02, s0[3] - h03);
                pl[j][2] = pack2(s1[0] - h10, s1[1] - h11);
                pl[j][3] = pack2(s1[2] - h12, s1[3] - h13);
            }

            // ---- O += P @ V (3-split)
#pragma unroll
            for (int j = 0; j < 4; j++) {
                const uint32_t va = (uint32_t)(((j << 4) + l15) * APITCH) * 2;
#pragma unroll
                for (int nt = 0; nt < 16; nt++) {
                    uint32_t bhv[2], blv[2];
                    LDX2T(bhv, SVHs + va + (uint32_t)(nt << 4));
                    LDX2T(blv, SVLs + va + (uint32_t)(nt << 4));
                    MMA16816(oacc[nt], ph[j], bhv);
                    MMA16816(oacc[nt], pl[j], bhv);
                    MMA16816(oacc[nt], ph[j], blv);
                }
            }
        }
    }
    __syncthreads();   // all compute done before O staging overwrites stage-0 smem

    // ---- normalize + stage O in smem (reuse stage-0 K/V region)
    {
        float* Ost = (float*)(sm + SOST);
        const float iv0 = 1.0f / l0, iv1 = 1.0f / l1;
        const int rl0 = (w << 4) + gid, rl1 = rl0 + 8;
#pragma unroll
        for (int nt = 0; nt < 16; nt++) {
            const int cc = (nt << 3) + (tig << 1);
            Ost[rl0 * OPITCH + cc]     = oacc[nt][0] * iv0;
            Ost[rl0 * OPITCH + cc + 1] = oacc[nt][1] * iv0;
            Ost[rl1 * OPITCH + cc]     = oacc[nt][2] * iv1;
            Ost[rl1 * OPITCH + cc + 1] = oacc[nt][3] * iv1;
        }
    }
    __syncthreads();

    // ---- write y2 hi/lo split [M, 6144]
    {
        const float* Ost = (const float*)(sm + SOST);
        const int kcb = h * HD_;
#pragma unroll
        for (int p = 0; p < 16; p++) {
            const int idx = tid + (p << 8);
            const int r = idx >> 5, c4 = (idx & 31) << 2;
            const float v0 = Ost[r * OPITCH + c4],     v1 = Ost[r * OPITCH + c4 + 1];
            const float v2f = Ost[r * OPITCH + c4 + 2], v3 = Ost[r * OPITCH + c4 + 3];
            const float h0 = bf16_round(v0), h1 = bf16_round(v1);
            const float h2 = bf16_round(v2f), h3 = bf16_round(v3);
            uint2 hp, lp;
            hp.x = pack2(h0, h1); hp.y = pack2(h2, h3);
            lp.x = pack2(v0 - h0, v1 - h1); lp.y = pack2(v2f - h2, v3 - h3);
            const size_t ro = (size_t)(b * T_ + q0 + r) * K3_;
            *(uint2*)&y2[ro + kcb + c4]        = hp;
            *(uint2*)&y2[ro + 2048 + kcb + c4] = lp;
            *(uint2*)&y2[ro + 4096 + kcb + c4] = hp;
        }
    }
}

// ---------------------------------------------------------------------------
extern "C" void kernel_launch(void* const* d_in, const int* in_sizes, int n_in,
                              void* d_out, int out_size)
{
    const float* x    = (const float*)d_in[0];   // [16,512,2048]
    const float* Wqkv = (const float*)d_in[1];   // [2048,6144]
    const float* Wout = (const float*)d_in[2];   // [2048,2048]
    float* out = (float*)d_out;                  // [16,512,2048]

    __nv_bfloat16 *q2, *k2, *v2, *a2, *b2q, *b2o, *y2;
    cudaGetSymbolAddress((void**)&q2,  g_q2);
    cudaGetSymbolAddress((void**)&k2,  g_k2);
    cudaGetSymbolAddress((void**)&v2,  g_v2);
    cudaGetSymbolAddress((void**)&a2,  g_a2);
    cudaGetSymbolAddress((void**)&b2q, g_b2q);
    cudaGetSymbolAddress((void**)&b2o, g_b2o);
    cudaGetSymbolAddress((void**)&y2,  g_y2);

    // 0) bf16 hi/lo conversions
    conv_a_kernel<<<(M_ * C_) / 1024, 256>>>(x, a2);
    conv_w_kernel<<<dim3(N3_ / 32, C_ / 32), 256>>>(Wqkv, b2q, N3_);
    conv_w_kernel<<<dim3(C_ / 32,  C_ / 32), 256>>>(Wout, b2o, C_);

    cudaFuncSetAttribute(gemm_qkv, cudaFuncAttributeMaxDynamicSharedMemorySize, G_SMEM_BYTES);
    cudaFuncSetAttribute(gemm_mma, cudaFuncAttributeMaxDynamicSharedMemorySize, G_SMEM_BYTES);

    // 1) q2/k2/v2 = rope(split(x @ Wqkv))  — fused epilogue
    gemm_qkv<<<dim3(N3_ / 128, M_ / 128), 256, G_SMEM_BYTES>>>(a2, b2q, q2, k2, v2);

    // 2) tensor-core causal flash attention -> y2 (split layout)
    cudaFuncSetAttribute(attention_tc, cudaFuncAttributeMaxDynamicSharedMemorySize, ATTN_SMEM);
    attention_tc<<<B_ * H_ * 4, 256, ATTN_SMEM>>>(q2, k2, v2, y2);

    // 3) out = y @ Wout   (mma.sync bf16 3-split)
    gemm_mma<<<dim3(C_ / 128, M_ / 128), 256, G_SMEM_BYTES>>>(y2, b2o, out, C_);
}